// round 16
// baseline (speedup 1.0000x reference)
#include <cuda_runtime.h>
#include <math.h>
#include <stdint.h>

#define JN 23
#define VMAX 400000

// Scratch (device globals — no allocation allowed)
__device__ float  g_A[JN * 12];     // per-joint 3x4 skinning matrices
__device__ float  g_off[3];         // random_dis + displacement
__device__ int    g_flag;           // rig-published flag (0 at load)
__device__ int    g_done;           // face-block completion counter
__device__ float4 g_verts[VMAX];    // posed verts (xyz, pad)
__device__ float4 g_nsum[VMAX];     // neighbor sum xyz + degree in .w

// ---------------------------------------------------------------------------
// Rig math run by block 0, warp 0 of k_skin (publishes g_A/g_off + g_flag).
// ---------------------------------------------------------------------------
__device__ void rig_compute(
    const float* __restrict__ joints,
    const float* __restrict__ j0in, const float* __restrict__ j2in,
    const float* __restrict__ j3in, const float* __restrict__ j4in,
    const float* __restrict__ j5in,
    const float* __restrict__ disp, const float* __restrict__ rdis,
    float (*sM)[12], float (*chain)[12], float* sA, float* soff)
{
    const int lane = threadIdx.x;   // < 32
    const float HALF_PI = 1.5707963267948966f;
    const int PAR[JN] = {-1,0,1,1,3,4,5,4,7,4,9,1,11,12,13,12,15,12,17,0,19,0,21};

    if (lane < JN) {
        float px = 0.f, py = 0.f, pz = 0.f;
        if (lane == 0)       { px = j0in[0]; py = j0in[1]; pz = j0in[2]; }
        else if (lane == 3)  { px = HALF_PI*tanhf(j2in[0]); py = HALF_PI*tanhf(j2in[1]); pz = HALF_PI*tanhf(j2in[2]); }
        else if (lane == 4)  { px = HALF_PI*tanhf(j3in[0]); py = HALF_PI*tanhf(j3in[1]); pz = HALF_PI*tanhf(j3in[2]); }
        else if (lane == 11) { px = HALF_PI*tanhf(j4in[0]); py = HALF_PI*tanhf(j4in[1]); pz = HALF_PI*tanhf(j4in[2]); }
        else if (lane == 12) { px = HALF_PI*tanhf(j5in[0]); py = HALF_PI*tanhf(j5in[1]); pz = HALF_PI*tanhf(j5in[2]); }

        float ang = sqrtf(px*px + py*py + pz*pz) + 1e-8f;
        float ax = px/ang, ay = py/ang, az = pz/ang;
        float K[9]  = {0.f, -az, ay,  az, 0.f, -ax,  -ay, ax, 0.f};
        float K2[9];
        #pragma unroll
        for (int r = 0; r < 3; r++)
            #pragma unroll
            for (int c = 0; c < 3; c++) {
                float s = 0.f;
                #pragma unroll
                for (int t = 0; t < 3; t++) s += K[r*3+t] * K[t*3+c];
                K2[r*3+c] = s;
            }
        float sn = sinf(ang), cs = cosf(ang);
        float R[9];
        #pragma unroll
        for (int e = 0; e < 9; e++) {
            float eye = (e == 0 || e == 4 || e == 8) ? 1.0f : 0.0f;
            R[e] = eye + sn * K[e] + (1.0f - cs) * K2[e];
        }
        float rel[3];
        #pragma unroll
        for (int k = 0; k < 3; k++) {
            rel[k] = joints[lane*3 + k];
            if (lane > 0) rel[k] -= joints[PAR[lane]*3 + k];
        }
        sM[lane][0]=R[0]; sM[lane][1]=R[1]; sM[lane][2] =R[2]; sM[lane][3] =rel[0];
        sM[lane][4]=R[3]; sM[lane][5]=R[4]; sM[lane][6] =R[5]; sM[lane][7] =rel[1];
        sM[lane][8]=R[6]; sM[lane][9]=R[7]; sM[lane][10]=R[8]; sM[lane][11]=rel[2];
    }
    if (lane < 3) soff[lane] = rdis[lane] + disp[lane];
    __syncwarp();

    if (lane == 0) {
        #pragma unroll
        for (int e = 0; e < 12; e++) chain[0][e] = sM[0][e];
        for (int i = 1; i < JN; i++) {
            const float* P = chain[PAR[i]];
            const float* M = sM[i];
            float* C = chain[i];
            #pragma unroll
            for (int r = 0; r < 3; r++) {
                #pragma unroll
                for (int cc = 0; cc < 3; cc++) {
                    C[r*4+cc] = P[r*4+0]*M[0*4+cc] + P[r*4+1]*M[1*4+cc] + P[r*4+2]*M[2*4+cc];
                }
                C[r*4+3] = P[r*4+0]*M[3] + P[r*4+1]*M[7] + P[r*4+2]*M[11] + P[r*4+3];
            }
        }
    }
    __syncwarp();

    if (lane < JN) {
        float jx = joints[lane*3+0], jy = joints[lane*3+1], jz = joints[lane*3+2];
        #pragma unroll
        for (int r = 0; r < 3; r++) {
            float corr = chain[lane][r*4+0]*jx + chain[lane][r*4+1]*jy + chain[lane][r*4+2]*jz;
            float a0 = chain[lane][r*4+0];
            float a1 = chain[lane][r*4+1];
            float a2 = chain[lane][r*4+2];
            float a3 = chain[lane][r*4+3] - corr;
            sA[lane*12 + r*4 + 0] = a0;  g_A[lane*12 + r*4 + 0] = a0;
            sA[lane*12 + r*4 + 1] = a1;  g_A[lane*12 + r*4 + 1] = a1;
            sA[lane*12 + r*4 + 2] = a2;  g_A[lane*12 + r*4 + 2] = a2;
            sA[lane*12 + r*4 + 3] = a3;  g_A[lane*12 + r*4 + 3] = a3;
        }
    }
    if (lane < 3) g_off[lane] = soff[lane];
    __syncwarp();

    if (lane == 0) {
        __threadfence();                 // g_A/g_off visible before flag
        *((volatile int*)&g_flag) = 1;   // publish
    }
}

// ---------------------------------------------------------------------------
// Kernel 1 (fused rig + skinning) — R12's measured-best form: 128-vert
// blocks, scalar T[12] inner loop. Resets g_done and lap_slot.
// ---------------------------------------------------------------------------
#define SKIN_B 128
__global__ void __launch_bounds__(SKIN_B)
k_skin(const float* __restrict__ verts_in,
       const float* __restrict__ skin,
       const float* __restrict__ joints,
       const float* __restrict__ j0in, const float* __restrict__ j2in,
       const float* __restrict__ j3in, const float* __restrict__ j4in,
       const float* __restrict__ j5in,
       const float* __restrict__ disp, const float* __restrict__ rdis,
       float* __restrict__ lap_slot,
       int V)
{
    __shared__ __align__(16) float tile[SKIN_B * JN];  // 11.8 KB
    __shared__ float sA[JN * 12];
    __shared__ float sM[JN][12];     // rig scratch (block 0 only)
    __shared__ float chain[JN][12];  // rig scratch (block 0 only)
    __shared__ float soff[3];

    const int base = blockIdx.x * SKIN_B;
    const int nv   = min(SKIN_B, V - base);

    if (threadIdx.x < 32) {
        if (blockIdx.x == 0) {
            rig_compute(joints, j0in, j2in, j3in, j4in, j5in, disp, rdis,
                        sM, chain, sA, soff);
        } else {
            if (threadIdx.x == 0) {
                while (*((volatile int*)&g_flag) == 0) { }
            }
            __syncwarp();
            __threadfence();
            for (int i = threadIdx.x; i < JN * 12; i += 32) sA[i] = g_A[i];
            if (threadIdx.x < 3) soff[threadIdx.x] = g_off[threadIdx.x];
        }
    } else {
        // warps 1..3: stage the weight tile (coalesced float4)
        const int t = threadIdx.x - 32;
        const int NT = SKIN_B - 32;
        if (nv == SKIN_B) {
            const float4* src = reinterpret_cast<const float4*>(skin + (size_t)base * JN);
            float4* dst = reinterpret_cast<float4*>(tile);
            for (int i = t; i < SKIN_B * JN / 4; i += NT) dst[i] = src[i];
        } else {
            const float* src = skin + (size_t)base * JN;
            for (int i = t; i < nv * JN; i += NT) tile[i] = src[i];
        }
    }
    __syncthreads();

    const int v = base + threadIdx.x;
    if (v == 0) { *lap_slot = 0.0f; g_done = 0; }
    if (threadIdx.x >= nv) return;

    float T[12];
    #pragma unroll
    for (int e = 0; e < 12; e++) T[e] = 0.0f;

    const float* s = tile + threadIdx.x * JN;
    #pragma unroll
    for (int j = 0; j < JN; j++) {
        float w = s[j];
        #pragma unroll
        for (int e = 0; e < 12; e++) T[e] += w * sA[j*12 + e];
    }

    float x = verts_in[3*v+0], y = verts_in[3*v+1], z = verts_in[3*v+2];
    float px = T[0]*x + T[1]*y + T[2] *z + T[3]  + soff[0];
    float py = T[4]*x + T[5]*y + T[6] *z + T[7]  + soff[1];
    float pz = T[8]*x + T[9]*y + T[10]*z + T[11] + soff[2];

    g_verts[v] = make_float4(px, py, pz, 0.0f);
    g_nsum[v]  = make_float4(0.0f, 0.0f, 0.0f, 0.0f);
}

// ---------------------------------------------------------------------------
// Kernel 2 (fused copy + scatter + lap-tail):
//   even bids: batch broadcast from g_verts (streaming stores) — exit.
//   odd bids, fid < nFaceB: face scatter, then counter rendezvous, then the
//     SAME blocks compute the Laplacian (2 verts/thread, L2-warm). No extra
//     spinning blocks (R14's mistake). 782 spinners < ~888 max-resident and
//     copy blocks always exit, so dispatch cannot starve -> no deadlock.
//   odd bids, fid >= nFaceB: exit.
// ---------------------------------------------------------------------------
__device__ __forceinline__ void red4(float4* p, float x, float y, float z, float w)
{
    asm volatile("red.global.add.v4.f32 [%0], {%1, %2, %3, %4};"
                 :: "l"(p), "f"(x), "f"(y), "f"(z), "f"(w) : "memory");
}

__device__ __forceinline__ void face_scatter(const int* __restrict__ faces, int f)
{
    int a = __ldg(&faces[3*f+0]);
    int b = __ldg(&faces[3*f+1]);
    int c = __ldg(&faces[3*f+2]);
    float4 va = __ldg(&g_verts[a]);
    float4 vb = __ldg(&g_verts[b]);
    float4 vc = __ldg(&g_verts[c]);
    red4(&g_nsum[a], vb.x + vc.x, vb.y + vc.y, vb.z + vc.z, 2.0f);
    red4(&g_nsum[b], va.x + vc.x, va.y + vc.y, va.z + vc.z, 2.0f);
    red4(&g_nsum[c], va.x + vb.x, va.y + vb.y, va.z + vb.z, 2.0f);
}

__device__ __forceinline__ void scatter3(int a, int b, int c,
                                         float4 va, float4 vb, float4 vc)
{
    red4(&g_nsum[a], vb.x + vc.x, vb.y + vc.y, vb.z + vc.z, 2.0f);
    red4(&g_nsum[b], va.x + vc.x, va.y + vc.y, va.z + vc.z, 2.0f);
    red4(&g_nsum[c], va.x + vb.x, va.y + vb.y, va.z + vb.z, 2.0f);
}

__global__ void __launch_bounds__(256)
k_fused(const int* __restrict__ faces, int F,
        float* __restrict__ out, int V, int B,
        int nFaceB, float* __restrict__ lap_slot)
{
    if ((blockIdx.x & 1) == 0) {
        // ---- copy block: write all B batches from g_verts ----
        const int cid = blockIdx.x >> 1;
        const int n4 = (V * 3) / 4;
        const int i = cid * 256 + threadIdx.x;
        if (i < n4) {
            const int f0 = 4 * i;
            const int v0 = f0 / 3;
            const int r  = f0 - 3 * v0;
            float4 A = __ldg(&g_verts[v0]);
            float4 Bv = __ldg(&g_verts[v0 + 1]);
            float4 val;
            if (r == 0)      val = make_float4(A.x, A.y, A.z, Bv.x);
            else if (r == 1) val = make_float4(A.y, A.z, Bv.x, Bv.y);
            else             val = make_float4(A.z, Bv.x, Bv.y, Bv.z);
            const size_t stride4 = (size_t)(V * 3) / 4;
            float4* o = reinterpret_cast<float4*>(out);
            #pragma unroll 4
            for (int b = 0; b < B; b++)
                __stcs(o + (size_t)b * stride4 + i, val);
        }
        return;
    }

    const int fid = blockIdx.x >> 1;
    if (fid >= nFaceB) return;

    // ---- face block: 4 consecutive faces per thread (1024/block) ----
    {
        const int tq   = fid * 256 + threadIdx.x;
        const int base = tq * 4;
        if (base + 3 < F) {
            const int4* fp = reinterpret_cast<const int4*>(faces) + (size_t)3 * tq;
            int4 q0 = __ldg(fp);
            int4 q1 = __ldg(fp + 1);
            int4 q2 = __ldg(fp + 2);
            float4 v0a = __ldg(&g_verts[q0.x]), v0b = __ldg(&g_verts[q0.y]), v0c = __ldg(&g_verts[q0.z]);
            float4 v1a = __ldg(&g_verts[q0.w]), v1b = __ldg(&g_verts[q1.x]), v1c = __ldg(&g_verts[q1.y]);
            float4 v2a = __ldg(&g_verts[q1.z]), v2b = __ldg(&g_verts[q1.w]), v2c = __ldg(&g_verts[q2.x]);
            float4 v3a = __ldg(&g_verts[q2.y]), v3b = __ldg(&g_verts[q2.z]), v3c = __ldg(&g_verts[q2.w]);
            scatter3(q0.x, q0.y, q0.z, v0a, v0b, v0c);
            scatter3(q0.w, q1.x, q1.y, v1a, v1b, v1c);
            scatter3(q1.z, q1.w, q2.x, v2a, v2b, v2c);
            scatter3(q2.y, q2.z, q2.w, v3a, v3b, v3c);
        } else if (base < F) {
            for (int f = base; f < F; f++) face_scatter(faces, f);
        }
    }

    // ---- rendezvous: all face blocks done scattering ----
    __syncthreads();
    if (threadIdx.x == 0) {
        __threadfence();                      // release reds
        atomicAdd(&g_done, 1);
        while (*((volatile int*)&g_done) < nFaceB) { __nanosleep(64); }
    }
    __syncthreads();
    __threadfence();                          // acquire before nsum reads

    // ---- lap phase: 2 verts per thread over the same 782 blocks ----
    const int half = nFaceB * 256;            // 200192
    const int idx = fid * 256 + threadIdx.x;  // < half
    float s = 0.0f;
    {
        float4 p1 = __ldg(&g_verts[idx]);
        float4 n1 = __ldcg(&g_nsum[idx]);
        const int v2 = idx + half;
        bool ok2 = (v2 < V);
        float4 p2 = ok2 ? __ldg(&g_verts[v2]) : make_float4(0,0,0,0);
        float4 n2 = ok2 ? __ldcg(&g_nsum[v2]) : make_float4(0,0,0,1);

        float d1 = fmaxf(n1.w, 1.0f);
        float i1 = __frcp_rn(d1);
        float lx = p1.x - n1.x * i1;
        float ly = p1.y - n1.y * i1;
        float lz = p1.z - n1.z * i1;
        s = lx*lx + ly*ly + lz*lz;

        float d2 = fmaxf(n2.w, 1.0f);
        float i2 = __frcp_rn(d2);
        float mx = p2.x - n2.x * i2;
        float my = p2.y - n2.y * i2;
        float mz = p2.z - n2.z * i2;
        s += mx*mx + my*my + mz*mz;
    }

    #pragma unroll
    for (int o = 16; o > 0; o >>= 1) s += __shfl_down_sync(0xffffffffu, s, o);

    __shared__ float ws[8];
    int lane = threadIdx.x & 31, w = threadIdx.x >> 5;
    if (lane == 0) ws[w] = s;
    __syncthreads();
    if (w == 0) {
        s = (lane < 8) ? ws[lane] : 0.0f;
        #pragma unroll
        for (int o = 4; o > 0; o >>= 1) s += __shfl_down_sync(0xffffffffu, s, o);
        if (lane == 0) atomicAdd(lap_slot, s);
    }
}

// ---------------------------------------------------------------------------
extern "C" void kernel_launch(void* const* d_in, const int* in_sizes, int n_in,
                              void* d_out, int out_size)
{
    const float* vertices = (const float*)d_in[0];
    const float* joints   = (const float*)d_in[1];
    const float* skin     = (const float*)d_in[2];
    const float* j0       = (const float*)d_in[3];
    const float* j2       = (const float*)d_in[4];
    const float* j3       = (const float*)d_in[5];
    const float* j4       = (const float*)d_in[6];
    const float* j5       = (const float*)d_in[7];
    const float* disp     = (const float*)d_in[8];
    const float* rdis     = (const float*)d_in[9];
    const int*   faces    = (const int*)d_in[10];

    int V = in_sizes[0] / 3;
    int F = in_sizes[10] / 3;
    float* out = (float*)d_out;
    int B = (out_size - 1) / (V * 3);
    float* lap_slot = out + (out_size - 1);

    k_skin<<<(V + SKIN_B - 1) / SKIN_B, SKIN_B>>>(
        vertices, skin, joints, j0, j2, j3, j4, j5, disp, rdis, lap_slot, V);

    // Fused copy/scatter/lap kernel, interleaved 1:1.
    int n4 = (V * 3) / 4;
    int nCopy  = (n4 + 255) / 256;       // 1172
    int nFaceB = (F + 1023) / 1024;      // 782
    int pairs  = nCopy > nFaceB ? nCopy : nFaceB;
    k_fused<<<pairs * 2, 256>>>(faces, F, out, V, B, nFaceB, lap_slot);
}

// round 17
// speedup vs baseline: 1.0837x; 1.0837x over previous
#include <cuda_runtime.h>
#include <math.h>
#include <stdint.h>

#define JN 23
#define VMAX 400000

// Scratch (device globals — no allocation allowed)
__device__ float  g_A[JN * 12];     // per-joint 3x4 skinning matrices
__device__ float  g_off[3];         // random_dis + displacement
__device__ int    g_flag;           // rig-published flag (0 at load)
__device__ float4 g_verts[VMAX];    // posed verts (xyz, pad)
__device__ float4 g_nsum[VMAX];     // neighbor sum xyz + degree in .w

// ---------------------------------------------------------------------------
// Rig math run by block 0, warp 0 of k_skin (publishes g_A/g_off + g_flag).
// ---------------------------------------------------------------------------
__device__ void rig_compute(
    const float* __restrict__ joints,
    const float* __restrict__ j0in, const float* __restrict__ j2in,
    const float* __restrict__ j3in, const float* __restrict__ j4in,
    const float* __restrict__ j5in,
    const float* __restrict__ disp, const float* __restrict__ rdis,
    float (*sM)[12], float (*chain)[12], float* sA, float* soff)
{
    const int lane = threadIdx.x;   // < 32
    const float HALF_PI = 1.5707963267948966f;
    const int PAR[JN] = {-1,0,1,1,3,4,5,4,7,4,9,1,11,12,13,12,15,12,17,0,19,0,21};

    if (lane < JN) {
        float px = 0.f, py = 0.f, pz = 0.f;
        if (lane == 0)       { px = j0in[0]; py = j0in[1]; pz = j0in[2]; }
        else if (lane == 3)  { px = HALF_PI*tanhf(j2in[0]); py = HALF_PI*tanhf(j2in[1]); pz = HALF_PI*tanhf(j2in[2]); }
        else if (lane == 4)  { px = HALF_PI*tanhf(j3in[0]); py = HALF_PI*tanhf(j3in[1]); pz = HALF_PI*tanhf(j3in[2]); }
        else if (lane == 11) { px = HALF_PI*tanhf(j4in[0]); py = HALF_PI*tanhf(j4in[1]); pz = HALF_PI*tanhf(j4in[2]); }
        else if (lane == 12) { px = HALF_PI*tanhf(j5in[0]); py = HALF_PI*tanhf(j5in[1]); pz = HALF_PI*tanhf(j5in[2]); }

        float ang = sqrtf(px*px + py*py + pz*pz) + 1e-8f;
        float ax = px/ang, ay = py/ang, az = pz/ang;
        float K[9]  = {0.f, -az, ay,  az, 0.f, -ax,  -ay, ax, 0.f};
        float K2[9];
        #pragma unroll
        for (int r = 0; r < 3; r++)
            #pragma unroll
            for (int c = 0; c < 3; c++) {
                float s = 0.f;
                #pragma unroll
                for (int t = 0; t < 3; t++) s += K[r*3+t] * K[t*3+c];
                K2[r*3+c] = s;
            }
        float sn = sinf(ang), cs = cosf(ang);
        float R[9];
        #pragma unroll
        for (int e = 0; e < 9; e++) {
            float eye = (e == 0 || e == 4 || e == 8) ? 1.0f : 0.0f;
            R[e] = eye + sn * K[e] + (1.0f - cs) * K2[e];
        }
        float rel[3];
        #pragma unroll
        for (int k = 0; k < 3; k++) {
            rel[k] = joints[lane*3 + k];
            if (lane > 0) rel[k] -= joints[PAR[lane]*3 + k];
        }
        sM[lane][0]=R[0]; sM[lane][1]=R[1]; sM[lane][2] =R[2]; sM[lane][3] =rel[0];
        sM[lane][4]=R[3]; sM[lane][5]=R[4]; sM[lane][6] =R[5]; sM[lane][7] =rel[1];
        sM[lane][8]=R[6]; sM[lane][9]=R[7]; sM[lane][10]=R[8]; sM[lane][11]=rel[2];
    }
    if (lane < 3) soff[lane] = rdis[lane] + disp[lane];
    __syncwarp();

    if (lane == 0) {
        #pragma unroll
        for (int e = 0; e < 12; e++) chain[0][e] = sM[0][e];
        for (int i = 1; i < JN; i++) {
            const float* P = chain[PAR[i]];
            const float* M = sM[i];
            float* C = chain[i];
            #pragma unroll
            for (int r = 0; r < 3; r++) {
                #pragma unroll
                for (int cc = 0; cc < 3; cc++) {
                    C[r*4+cc] = P[r*4+0]*M[0*4+cc] + P[r*4+1]*M[1*4+cc] + P[r*4+2]*M[2*4+cc];
                }
                C[r*4+3] = P[r*4+0]*M[3] + P[r*4+1]*M[7] + P[r*4+2]*M[11] + P[r*4+3];
            }
        }
    }
    __syncwarp();

    if (lane < JN) {
        float jx = joints[lane*3+0], jy = joints[lane*3+1], jz = joints[lane*3+2];
        #pragma unroll
        for (int r = 0; r < 3; r++) {
            float corr = chain[lane][r*4+0]*jx + chain[lane][r*4+1]*jy + chain[lane][r*4+2]*jz;
            float a0 = chain[lane][r*4+0];
            float a1 = chain[lane][r*4+1];
            float a2 = chain[lane][r*4+2];
            float a3 = chain[lane][r*4+3] - corr;
            sA[lane*12 + r*4 + 0] = a0;  g_A[lane*12 + r*4 + 0] = a0;
            sA[lane*12 + r*4 + 1] = a1;  g_A[lane*12 + r*4 + 1] = a1;
            sA[lane*12 + r*4 + 2] = a2;  g_A[lane*12 + r*4 + 2] = a2;
            sA[lane*12 + r*4 + 3] = a3;  g_A[lane*12 + r*4 + 3] = a3;
        }
    }
    if (lane < 3) g_off[lane] = soff[lane];
    __syncwarp();

    if (lane == 0) {
        __threadfence();                 // g_A/g_off visible before flag
        *((volatile int*)&g_flag) = 1;   // publish
    }
}

// ---------------------------------------------------------------------------
// Kernel 1 (fused rig + skinning + broadcast): 128-vert blocks, scalar T[12]
// inner loop; each block then broadcasts its 384 floats to all B batches
// with coalesced streaming float4 stores. The 77 MB output stream rides in
// skin's idle DRAM headroom (measured +6.5 µs vs +9 µs when interleaved with
// the scatter).
// ---------------------------------------------------------------------------
#define SKIN_B 128
__global__ void __launch_bounds__(SKIN_B)
k_skin(const float* __restrict__ verts_in,
       const float* __restrict__ skin,
       const float* __restrict__ joints,
       const float* __restrict__ j0in, const float* __restrict__ j2in,
       const float* __restrict__ j3in, const float* __restrict__ j4in,
       const float* __restrict__ j5in,
       const float* __restrict__ disp, const float* __restrict__ rdis,
       float* __restrict__ out, int B,
       float* __restrict__ lap_slot,
       int V)
{
    __shared__ __align__(16) float tile[SKIN_B * JN];  // 11.8 KB
    __shared__ __align__(16) float sv[SKIN_B * 3];     // staged output (1.5 KB)
    __shared__ float sA[JN * 12];
    __shared__ float sM[JN][12];     // rig scratch (block 0 only)
    __shared__ float chain[JN][12];  // rig scratch (block 0 only)
    __shared__ float soff[3];

    const int base = blockIdx.x * SKIN_B;
    const int nv   = min(SKIN_B, V - base);

    if (threadIdx.x < 32) {
        if (blockIdx.x == 0) {
            rig_compute(joints, j0in, j2in, j3in, j4in, j5in, disp, rdis,
                        sM, chain, sA, soff);
        } else {
            if (threadIdx.x == 0) {
                while (*((volatile int*)&g_flag) == 0) { }
            }
            __syncwarp();
            __threadfence();
            for (int i = threadIdx.x; i < JN * 12; i += 32) sA[i] = g_A[i];
            if (threadIdx.x < 3) soff[threadIdx.x] = g_off[threadIdx.x];
        }
    } else {
        // warps 1..3: stage the weight tile (coalesced float4)
        const int t = threadIdx.x - 32;
        const int NT = SKIN_B - 32;
        if (nv == SKIN_B) {
            const float4* src = reinterpret_cast<const float4*>(skin + (size_t)base * JN);
            float4* dst = reinterpret_cast<float4*>(tile);
            for (int i = t; i < SKIN_B * JN / 4; i += NT) dst[i] = src[i];
        } else {
            const float* src = skin + (size_t)base * JN;
            for (int i = t; i < nv * JN; i += NT) tile[i] = src[i];
        }
    }
    __syncthreads();

    const int v = base + threadIdx.x;
    if (v == 0) *lap_slot = 0.0f;

    if (threadIdx.x < nv) {
        float T[12];
        #pragma unroll
        for (int e = 0; e < 12; e++) T[e] = 0.0f;

        const float* s = tile + threadIdx.x * JN;
        #pragma unroll
        for (int j = 0; j < JN; j++) {
            float w = s[j];
            #pragma unroll
            for (int e = 0; e < 12; e++) T[e] += w * sA[j*12 + e];
        }

        float x = verts_in[3*v+0], y = verts_in[3*v+1], z = verts_in[3*v+2];
        float px = T[0]*x + T[1]*y + T[2] *z + T[3]  + soff[0];
        float py = T[4]*x + T[5]*y + T[6] *z + T[7]  + soff[1];
        float pz = T[8]*x + T[9]*y + T[10]*z + T[11] + soff[2];

        g_verts[v] = make_float4(px, py, pz, 0.0f);  // stays in L2 for scatter
        g_nsum[v]  = make_float4(0.0f, 0.0f, 0.0f, 0.0f);

        sv[3*threadIdx.x + 0] = px;
        sv[3*threadIdx.x + 1] = py;
        sv[3*threadIdx.x + 2] = pz;
    }
    __syncthreads();

    // ---- broadcast this block's verts to all B batches (streaming) ----
    if (nv == SKIN_B) {
        const int N4 = SKIN_B * 3 / 4;              // 96 float4
        const float4* svv = reinterpret_cast<const float4*>(sv);
        float4* o = reinterpret_cast<float4*>(out);
        const size_t stride4 = (size_t)V * 3 / 4;
        const size_t base4 = (size_t)blockIdx.x * N4;
        for (int idx = threadIdx.x; idx < N4 * B; idx += SKIN_B) {
            int b = idx / N4;
            int i = idx - b * N4;
            __stcs(o + (size_t)b * stride4 + base4 + i, svv[i]);
        }
    } else {
        for (int idx = threadIdx.x; idx < nv * 3; idx += SKIN_B) {
            float val = sv[idx];
            for (int b = 0; b < B; b++)
                out[(size_t)b * V * 3 + (size_t)base * 3 + idx] = val;
        }
    }
}

// ---------------------------------------------------------------------------
// Kernel 2: face scatter ONLY — 782 blocks, 4 faces/thread, int4 index
// loads, all 12 gathers issued before the 12 red4. No co-resident spinners,
// no copy blocks: runs at the L2 gather+atomic floor.
// ---------------------------------------------------------------------------
__device__ __forceinline__ void red4(float4* p, float x, float y, float z, float w)
{
    asm volatile("red.global.add.v4.f32 [%0], {%1, %2, %3, %4};"
                 :: "l"(p), "f"(x), "f"(y), "f"(z), "f"(w) : "memory");
}

__device__ __forceinline__ void face_scatter(const int* __restrict__ faces, int f)
{
    int a = __ldg(&faces[3*f+0]);
    int b = __ldg(&faces[3*f+1]);
    int c = __ldg(&faces[3*f+2]);
    float4 va = __ldg(&g_verts[a]);
    float4 vb = __ldg(&g_verts[b]);
    float4 vc = __ldg(&g_verts[c]);
    red4(&g_nsum[a], vb.x + vc.x, vb.y + vc.y, vb.z + vc.z, 2.0f);
    red4(&g_nsum[b], va.x + vc.x, va.y + vc.y, va.z + vc.z, 2.0f);
    red4(&g_nsum[c], va.x + vb.x, va.y + vb.y, va.z + vb.z, 2.0f);
}

__device__ __forceinline__ void scatter3(int a, int b, int c,
                                         float4 va, float4 vb, float4 vc)
{
    red4(&g_nsum[a], vb.x + vc.x, vb.y + vc.y, vb.z + vc.z, 2.0f);
    red4(&g_nsum[b], va.x + vc.x, va.y + vc.y, va.z + vc.z, 2.0f);
    red4(&g_nsum[c], va.x + vb.x, va.y + vb.y, va.z + vb.z, 2.0f);
}

__global__ void __launch_bounds__(256)
k_faces(const int* __restrict__ faces, int F)
{
    const int tq   = blockIdx.x * 256 + threadIdx.x;
    const int base = tq * 4;
    if (base + 3 < F) {
        const int4* fp = reinterpret_cast<const int4*>(faces) + (size_t)3 * tq;
        int4 q0 = __ldg(fp);
        int4 q1 = __ldg(fp + 1);
        int4 q2 = __ldg(fp + 2);
        float4 v0a = __ldg(&g_verts[q0.x]), v0b = __ldg(&g_verts[q0.y]), v0c = __ldg(&g_verts[q0.z]);
        float4 v1a = __ldg(&g_verts[q0.w]), v1b = __ldg(&g_verts[q1.x]), v1c = __ldg(&g_verts[q1.y]);
        float4 v2a = __ldg(&g_verts[q1.z]), v2b = __ldg(&g_verts[q1.w]), v2c = __ldg(&g_verts[q2.x]);
        float4 v3a = __ldg(&g_verts[q2.y]), v3b = __ldg(&g_verts[q2.z]), v3c = __ldg(&g_verts[q2.w]);
        scatter3(q0.x, q0.y, q0.z, v0a, v0b, v0c);
        scatter3(q0.w, q1.x, q1.y, v1a, v1b, v1c);
        scatter3(q1.z, q1.w, q2.x, v2a, v2b, v2c);
        scatter3(q2.y, q2.z, q2.w, v3a, v3b, v3c);
    } else if (base < F) {
        for (int f = base; f < F; f++) face_scatter(faces, f);
    }
}

// ---------------------------------------------------------------------------
// Kernel 3: Laplacian reduction — 1 vertex/thread (measured best).
// ---------------------------------------------------------------------------
__global__ void __launch_bounds__(256)
k_lap(float* __restrict__ lap_slot, int V)
{
    const int v = blockIdx.x * blockDim.x + threadIdx.x;
    float s = 0.0f;
    if (v < V) {
        float4 p = __ldg(&g_verts[v]);
        float4 n = __ldg(&g_nsum[v]);
        float d = fmaxf(n.w, 1.0f);
        float inv = __frcp_rn(d);
        float lx = p.x - n.x * inv;
        float ly = p.y - n.y * inv;
        float lz = p.z - n.z * inv;
        s = lx*lx + ly*ly + lz*lz;
    }

    #pragma unroll
    for (int o = 16; o > 0; o >>= 1) s += __shfl_down_sync(0xffffffffu, s, o);

    __shared__ float ws[8];
    int lane = threadIdx.x & 31, w = threadIdx.x >> 5;
    if (lane == 0) ws[w] = s;
    __syncthreads();
    if (w == 0) {
        s = (lane < (int)(blockDim.x >> 5)) ? ws[lane] : 0.0f;
        #pragma unroll
        for (int o = 4; o > 0; o >>= 1) s += __shfl_down_sync(0xffffffffu, s, o);
        if (lane == 0) atomicAdd(lap_slot, s);
    }
}

// ---------------------------------------------------------------------------
extern "C" void kernel_launch(void* const* d_in, const int* in_sizes, int n_in,
                              void* d_out, int out_size)
{
    const float* vertices = (const float*)d_in[0];
    const float* joints   = (const float*)d_in[1];
    const float* skin     = (const float*)d_in[2];
    const float* j0       = (const float*)d_in[3];
    const float* j2       = (const float*)d_in[4];
    const float* j3       = (const float*)d_in[5];
    const float* j4       = (const float*)d_in[6];
    const float* j5       = (const float*)d_in[7];
    const float* disp     = (const float*)d_in[8];
    const float* rdis     = (const float*)d_in[9];
    const int*   faces    = (const int*)d_in[10];

    int V = in_sizes[0] / 3;
    int F = in_sizes[10] / 3;
    float* out = (float*)d_out;
    int B = (out_size - 1) / (V * 3);
    float* lap_slot = out + (out_size - 1);

    k_skin<<<(V + SKIN_B - 1) / SKIN_B, SKIN_B>>>(
        vertices, skin, joints, j0, j2, j3, j4, j5, disp, rdis,
        out, B, lap_slot, V);

    int nFaceB = (F + 1023) / 1024;      // 782
    k_faces<<<nFaceB, 256>>>(faces, F);

    k_lap<<<(V + 255) / 256, 256>>>(lap_slot, V);
}